// round 3
// baseline (speedup 1.0000x reference)
#include <cuda_runtime.h>
#include <cstdint>

#define B_   128
#define S_   1024
#define I_   128
#define H_   256
#define OFF_SLOPE 0.001f

// ---------------- device scratch (static, no allocations) ----------------
__device__ __align__(16) float g_G[134217728];      // [B*S][1024] = 512 MB
__device__ __align__(16) float g_hbuf[2][B_ * H_];  // double-buffered h exchange

// ---------------- init: h0 = 0 (every launch/replay) ----
__global__ void init_k() {
    unsigned t = blockIdx.x * blockDim.x + threadIdx.x;
    for (unsigned i = t; i < 2u * B_ * H_; i += gridDim.x * blockDim.x)
        ((float*)g_hbuf)[i] = 0.f;
}

// ---------------- phase A: G = x @ W + bias  (fp32 tiled SGEMM) ----------
// M=131072, K=128, N=1024. Block tile 64(M) x 128(N), BK=32, 256 threads,
// thread tile 8x4 (A-frag broadcast per warp, B-frag conflict-free).
__global__ __launch_bounds__(256) void gemm_xw(const float* __restrict__ X,
                                               const float* __restrict__ Wm,
                                               const float* __restrict__ bias) {
    __shared__ __align__(16) float As[32][68];    // [k][m] transposed, padded
    __shared__ __align__(16) float Bs[32][128];   // [k][n]
    const int m0 = blockIdx.x * 64;
    const int n0 = blockIdx.y * 128;
    const int tid = threadIdx.x;
    const int tx = tid & 31, ty = tid >> 5;

    float4 acc[8];
#pragma unroll
    for (int r = 0; r < 8; r++) acc[r] = make_float4(0.f, 0.f, 0.f, 0.f);

    for (int kt = 0; kt < 128; kt += 32) {
#pragma unroll
        for (int i = 0; i < 2; i++) {
            int lin = tid + i * 256;          // 0..511
            int m = lin >> 3, k4 = lin & 7;
            float4 v = reinterpret_cast<const float4*>(X)[(size_t)(m0 + m) * 32 + (kt >> 2) + k4];
            As[k4 * 4 + 0][m] = v.x; As[k4 * 4 + 1][m] = v.y;
            As[k4 * 4 + 2][m] = v.z; As[k4 * 4 + 3][m] = v.w;
        }
#pragma unroll
        for (int i = 0; i < 4; i++) {
            int lin = tid + i * 256;          // 0..1023
            int k = lin >> 5, n4 = lin & 31;
            reinterpret_cast<float4*>(&Bs[k][0])[n4] =
                reinterpret_cast<const float4*>(Wm)[(size_t)(kt + k) * 256 + (n0 >> 2) + n4];
        }
        __syncthreads();
#pragma unroll
        for (int k = 0; k < 32; k++) {
            float4 b4 = reinterpret_cast<float4*>(&Bs[k][0])[tx];
            const float4* Ap = reinterpret_cast<const float4*>(&As[k][ty * 8]);
            float4 a0 = Ap[0], a1 = Ap[1];
            float am[8] = {a0.x, a0.y, a0.z, a0.w, a1.x, a1.y, a1.z, a1.w};
#pragma unroll
            for (int r = 0; r < 8; r++) {
                acc[r].x += am[r] * b4.x; acc[r].y += am[r] * b4.y;
                acc[r].z += am[r] * b4.z; acc[r].w += am[r] * b4.w;
            }
        }
        __syncthreads();
    }
    float4 bv = reinterpret_cast<const float4*>(bias)[(n0 >> 2) + tx];
#pragma unroll
    for (int r = 0; r < 8; r++) {
        int m = m0 + ty * 8 + r;
        float4 o = acc[r];
        o.x += bv.x; o.y += bv.y; o.z += bv.z; o.w += bv.w;
        reinterpret_cast<float4*>(g_G)[(size_t)m * 256 + (n0 >> 2) + tx] = o;
    }
}

// ---------------- phase B: persistent recurrent kernel -------------------
__device__ __forceinline__ float sigf(float x) { return 1.0f / (1.0f + __expf(-x)); }

// 128 CTAs = 16 clusters of 8. Cluster == batch group (8 batches); the 8
// CTAs within a cluster each own 32 h-units (128 gate cols). U slice is
// register-resident for the whole sequence; c/h carries in registers.
// h exchange via L2 (g_hbuf) ordered by the cluster barrier.
__global__ __launch_bounds__(256, 1) __cluster_dims__(8, 1, 1) void plstm_rec(
    const float* __restrict__ U, const float* __restrict__ ts,
    const float* __restrict__ Per, const float* __restrict__ Shf,
    const float* __restrict__ Oe, float* __restrict__ out, int writeTails) {
    __shared__ __align__(16) float hs_sm[8 * 256];  // staged h for 8 batches
    __shared__ __align__(16) float red[8192];       // [kc][b][j][g] partials

    const int tid = threadIdx.x;
    const int grp = blockIdx.x >> 3;
    const int hslc = blockIdx.x & 7;
    const int bg0 = grp * 8;
    const int hs = hslc * 32;
    const int kc = tid >> 5;     // matmul role: K-chunk (= warp id)
    const int jj = tid & 31;     // matmul role: h-unit in slice
    const int ob = kc;           // owner role: batch in group
    const int oj = jj;           // owner role: h-unit in slice
    const int jg = hs + oj;

    // per-owner phased-gate constants
    const float pv = fabsf(Per[jg]);
    const float sv = Shf[jg];
    const float oe = fabsf(Oe[jg]);
    const float on_end = oe * pv;
    const float on_mid = (oe * 0.5f) * pv;

    // register-resident U slice: U[kc*32 + kk][g*256 + hs + jj]
    float Ureg[32][4];
    {
        const float* Ub = U + (size_t)(kc * 32) * 1024 + hs + jj;
#pragma unroll
        for (int kk = 0; kk < 32; kk++)
#pragma unroll
            for (int g = 0; g < 4; g++)
                Ureg[kk][g] = Ub[(size_t)kk * 1024 + g * 256];
    }

    float ccar = 0.f, hcar = 0.f;
    const float* tsrow = ts + (size_t)(bg0 + ob) * S_;
    const float* Gbase = g_G + (size_t)(bg0 + ob) * S_ * 1024 + hs + oj;

    // prefetch step-0 owner inputs
    float Gi = Gbase[0], Gf = Gbase[256], Gg = Gbase[512], Go = Gbase[768];
    float tt = tsrow[0];

    for (int s = 0; s < S_; s++) {
        const int cur = s & 1, nxt = cur ^ 1;

        // stage h for this group (L2-coherent reads)
        const float4* hbp = reinterpret_cast<const float4*>(&g_hbuf[cur][bg0 * H_]);
        float4* hsp = reinterpret_cast<float4*>(hs_sm);
        hsp[tid]       = __ldcg(hbp + tid);
        hsp[tid + 256] = __ldcg(hbp + tid + 256);
        __syncthreads();

        // matmul partials: 8 batches x 4 gates over this thread's 32 K values
        float acc[8][4];
#pragma unroll
        for (int b = 0; b < 8; b++) {
            acc[b][0] = 0.f; acc[b][1] = 0.f; acc[b][2] = 0.f; acc[b][3] = 0.f;
        }
#pragma unroll
        for (int b = 0; b < 8; b++) {
            const float4* hp = reinterpret_cast<const float4*>(&hs_sm[b * 256 + kc * 32]);
#pragma unroll
            for (int k4 = 0; k4 < 8; k4++) {
                float4 h4 = hp[k4];
                const int kk = k4 * 4;
#pragma unroll
                for (int g = 0; g < 4; g++) {
                    acc[b][g] += h4.x * Ureg[kk + 0][g];
                    acc[b][g] += h4.y * Ureg[kk + 1][g];
                    acc[b][g] += h4.z * Ureg[kk + 2][g];
                    acc[b][g] += h4.w * Ureg[kk + 3][g];
                }
            }
        }

        // write partials, reduce across 8 K-chunks
#pragma unroll
        for (int b = 0; b < 8; b++)
            reinterpret_cast<float4*>(red)[(kc * 8 + b) * 32 + jj] =
                make_float4(acc[b][0], acc[b][1], acc[b][2], acc[b][3]);
        __syncthreads();

        float4 sum = make_float4(0.f, 0.f, 0.f, 0.f);
#pragma unroll
        for (int q = 0; q < 8; q++) {
            float4 p = reinterpret_cast<const float4*>(red)[(q * 8 + ob) * 32 + oj];
            sum.x += p.x; sum.y += p.y; sum.z += p.z; sum.w += p.w;
        }

        // LSTM cell + phased time gate (owner thread owns (b, j) carries)
        float it = sigf(Gi + sum.x);
        float ft = sigf(Gf + sum.y);
        float gt = tanhf(Gg + sum.z);
        float ot = sigf(Go + sum.w);
        float cn = ft * ccar + it * gt;
        float hn = ot * tanhf(cn);

        float ic = fmodf(tt + sv, pv);
        float mask;
        if (ic <= on_mid)      mask = ic / on_mid;
        else if (ic <= on_end) mask = (on_end - ic) / on_mid;
        else                   mask = OFF_SLOPE * (ic / pv);

        ccar = mask * cn + (1.f - mask) * ccar;
        float h2 = mask * hn + (1.f - mask) * hcar;
        hcar = h2;

        // publish h, then arrive (release). Fill the skew window with the
        // out-store and next-step G/ts prefetch, then wait (acquire).
        g_hbuf[nxt][(bg0 + ob) * H_ + jg] = h2;
        asm volatile("barrier.cluster.arrive.aligned;" ::: "memory");

        out[((size_t)(bg0 + ob) * S_ + s) * H_ + jg] = h2;
        if (s + 1 < S_) {
            const float* Gp = Gbase + (size_t)(s + 1) * 1024;
            Gi = Gp[0]; Gf = Gp[256]; Gg = Gp[512]; Go = Gp[768];
            tt = tsrow[s + 1];
        }

        asm volatile("barrier.cluster.wait.aligned;" ::: "memory");
    }

    if (writeTails) {
        const size_t baseT = (size_t)B_ * S_ * H_;
        out[baseT + (size_t)(bg0 + ob) * H_ + jg] = hcar;                    // h_T
        out[baseT + (size_t)B_ * H_ + (size_t)(bg0 + ob) * H_ + jg] = ccar;  // c_T
    }
}

// ---------------- launch ----------------
extern "C" void kernel_launch(void* const* d_in, const int* in_sizes, int n_in,
                              void* d_out, int out_size) {
    const float* x    = (const float*)d_in[0];
    const float* ts   = (const float*)d_in[1];
    const float* W    = (const float*)d_in[2];
    const float* U    = (const float*)d_in[3];
    const float* bias = (const float*)d_in[4];
    const float* Per  = (const float*)d_in[5];
    const float* Shf  = (const float*)d_in[6];
    const float* Oe   = (const float*)d_in[7];
    float* out = (float*)d_out;

    init_k<<<64, 256>>>();

    dim3 gg(131072 / 64, 1024 / 128);
    gemm_xw<<<gg, 256>>>(x, W, bias);

    const long long need = (long long)B_ * S_ * H_ + 2LL * B_ * H_;
    int writeTails = ((long long)out_size >= need) ? 1 : 0;
    plstm_rec<<<128, 256>>>(U, ts, Per, Shf, Oe, out, writeTails);
}

// round 4
// speedup vs baseline: 1.0344x; 1.0344x over previous
#include <cuda_runtime.h>
#include <cstdint>

#define B_   128
#define S_   1024
#define I_   128
#define H_   256
#define OFF_SLOPE 0.001f

// ---------------- device scratch (static, no allocations) ----------------
__device__ __align__(16) float g_G[134217728];      // [B*S][1024] = 512 MB
__device__ __align__(16) float g_hbuf[2][B_ * H_];  // double-buffered h exchange
__device__ unsigned g_cnt[16];                      // per-group arrival counters

// ---------------- init: reset counters + h0 = 0 (every launch/replay) ----
__global__ void init_k() {
    unsigned t = blockIdx.x * blockDim.x + threadIdx.x;
    if (t < 16) g_cnt[t] = 0u;
    for (unsigned i = t; i < 2u * B_ * H_; i += gridDim.x * blockDim.x)
        ((float*)g_hbuf)[i] = 0.f;
}

// ---------------- phase A: G = x @ W + bias  (fp32 tiled SGEMM) ----------
__global__ __launch_bounds__(256) void gemm_xw(const float* __restrict__ X,
                                               const float* __restrict__ Wm,
                                               const float* __restrict__ bias) {
    __shared__ __align__(16) float As[32][68];    // [k][m] transposed, padded
    __shared__ __align__(16) float Bs[32][128];   // [k][n]
    const int m0 = blockIdx.x * 64;
    const int n0 = blockIdx.y * 128;
    const int tid = threadIdx.x;
    const int tx = tid & 31, ty = tid >> 5;

    float4 acc[8];
#pragma unroll
    for (int r = 0; r < 8; r++) acc[r] = make_float4(0.f, 0.f, 0.f, 0.f);

    for (int kt = 0; kt < 128; kt += 32) {
#pragma unroll
        for (int i = 0; i < 2; i++) {
            int lin = tid + i * 256;
            int m = lin >> 3, k4 = lin & 7;
            float4 v = reinterpret_cast<const float4*>(X)[(size_t)(m0 + m) * 32 + (kt >> 2) + k4];
            As[k4 * 4 + 0][m] = v.x; As[k4 * 4 + 1][m] = v.y;
            As[k4 * 4 + 2][m] = v.z; As[k4 * 4 + 3][m] = v.w;
        }
#pragma unroll
        for (int i = 0; i < 4; i++) {
            int lin = tid + i * 256;
            int k = lin >> 5, n4 = lin & 31;
            reinterpret_cast<float4*>(&Bs[k][0])[n4] =
                reinterpret_cast<const float4*>(Wm)[(size_t)(kt + k) * 256 + (n0 >> 2) + n4];
        }
        __syncthreads();
#pragma unroll
        for (int k = 0; k < 32; k++) {
            float4 b4 = reinterpret_cast<float4*>(&Bs[k][0])[tx];
            const float4* Ap = reinterpret_cast<const float4*>(&As[k][ty * 8]);
            float4 a0 = Ap[0], a1 = Ap[1];
            float am[8] = {a0.x, a0.y, a0.z, a0.w, a1.x, a1.y, a1.z, a1.w};
#pragma unroll
            for (int r = 0; r < 8; r++) {
                acc[r].x += am[r] * b4.x; acc[r].y += am[r] * b4.y;
                acc[r].z += am[r] * b4.z; acc[r].w += am[r] * b4.w;
            }
        }
        __syncthreads();
    }
    float4 bv = reinterpret_cast<const float4*>(bias)[(n0 >> 2) + tx];
#pragma unroll
    for (int r = 0; r < 8; r++) {
        int m = m0 + ty * 8 + r;
        float4 o = acc[r];
        o.x += bv.x; o.y += bv.y; o.z += bv.z; o.w += bv.w;
        reinterpret_cast<float4*>(g_G)[(size_t)m * 256 + (n0 >> 2) + tx] = o;
    }
}

// ---------------- phase B: persistent recurrent kernel -------------------
__device__ __forceinline__ float sigf(float x) { return 1.0f / (1.0f + __expf(-x)); }

__device__ __forceinline__ unsigned ld_acq(const unsigned* p) {
    unsigned v;
    asm volatile("ld.global.acquire.gpu.u32 %0, [%1];" : "=r"(v) : "l"(p) : "memory");
    return v;
}
__device__ __forceinline__ void red_release(unsigned* p) {
    asm volatile("red.release.gpu.global.add.u32 [%0], 1;" :: "l"(p) : "memory");
}
__device__ __forceinline__ float4 ldcg4(const float4* p) {
    float4 v;
    asm volatile("ld.global.cg.v4.f32 {%0,%1,%2,%3}, [%4];"
                 : "=f"(v.x), "=f"(v.y), "=f"(v.z), "=f"(v.w) : "l"(p));
    return v;
}

// 128 CTAs = 16 groups (8 batches) x 8 h-slices (32 h-units = 128 gate cols).
// U slice register-resident; h read directly from L2 (uniform broadcast
// ldcg inside matmul); per-WARP release-arrive / acquire-poll barrier
// (64 warps per group). One __syncthreads per step (reduction buffer).
__global__ __launch_bounds__(256, 1) void plstm_rec(
    const float* __restrict__ U, const float* __restrict__ ts,
    const float* __restrict__ Per, const float* __restrict__ Shf,
    const float* __restrict__ Oe, float* __restrict__ out, int writeTails) {
    __shared__ __align__(16) float red[8192];   // [kc][b][j][g] partials, 32 KB

    const int tid = threadIdx.x;
    const int lane = tid & 31;
    const int grp = blockIdx.x >> 3;
    const int hslc = blockIdx.x & 7;
    const int bg0 = grp * 8;
    const int hs = hslc * 32;
    const int kc = tid >> 5;     // matmul role: K-chunk (= warp id)
    const int jj = tid & 31;     // matmul role: h-unit in slice
    const int ob = kc;           // owner role: batch in group
    const int oj = jj;           // owner role: h-unit in slice
    const int jg = hs + oj;
    unsigned* cnt = &g_cnt[grp];

    const float pv = fabsf(Per[jg]);
    const float sv = Shf[jg];
    const float oe = fabsf(Oe[jg]);
    const float on_end = oe * pv;
    const float on_mid = (oe * 0.5f) * pv;

    // register-resident U slice: U[kc*32 + kk][g*256 + hs + jj]
    float Ureg[32][4];
    {
        const float* Ub = U + (size_t)(kc * 32) * 1024 + hs + jj;
#pragma unroll
        for (int kk = 0; kk < 32; kk++)
#pragma unroll
            for (int g = 0; g < 4; g++)
                Ureg[kk][g] = Ub[(size_t)kk * 1024 + g * 256];
    }

    float ccar = 0.f, hcar = 0.f;
    const float* tsrow = ts + (size_t)(bg0 + ob) * S_;
    const float* Gbase = g_G + (size_t)(bg0 + ob) * S_ * 1024 + hs + oj;

    // prefetch step-0 owner inputs
    float Gi = Gbase[0], Gf = Gbase[256], Gg = Gbase[512], Go = Gbase[768];
    float tt = tsrow[0];

    for (int s = 0; s < S_; s++) {
        const int cur = s & 1, nxt = cur ^ 1;

        // acquire-poll: wait until all 64 warps of the group arrived step s-1
        if (s > 0) {
            const unsigned tgt = 64u * (unsigned)s;
            if (lane == 0) while (ld_acq(cnt) < tgt) {}
            __syncwarp();
        }

        // matmul partials: 8 batches x 4 gates over this thread's 32 K values
        // h read as uniform (broadcast) float4 ldcg straight from L2.
        float acc[8][4];
#pragma unroll
        for (int b = 0; b < 8; b++) {
            acc[b][0] = 0.f; acc[b][1] = 0.f; acc[b][2] = 0.f; acc[b][3] = 0.f;
        }
#pragma unroll
        for (int b = 0; b < 8; b++) {
            const float4* hp = reinterpret_cast<const float4*>(
                &g_hbuf[cur][(bg0 + b) * H_ + kc * 32]);
            float4 h4v[8];
#pragma unroll
            for (int k4 = 0; k4 < 8; k4++) h4v[k4] = ldcg4(hp + k4);
#pragma unroll
            for (int k4 = 0; k4 < 8; k4++) {
                float4 h4 = h4v[k4];
                const int kk = k4 * 4;
#pragma unroll
                for (int g = 0; g < 4; g++) {
                    acc[b][g] += h4.x * Ureg[kk + 0][g];
                    acc[b][g] += h4.y * Ureg[kk + 1][g];
                    acc[b][g] += h4.z * Ureg[kk + 2][g];
                    acc[b][g] += h4.w * Ureg[kk + 3][g];
                }
            }
        }

        // write partials, reduce across 8 K-chunks
#pragma unroll
        for (int b = 0; b < 8; b++)
            reinterpret_cast<float4*>(red)[(kc * 8 + b) * 32 + jj] =
                make_float4(acc[b][0], acc[b][1], acc[b][2], acc[b][3]);
        __syncthreads();

        float4 sum = make_float4(0.f, 0.f, 0.f, 0.f);
#pragma unroll
        for (int q = 0; q < 8; q++) {
            float4 p = reinterpret_cast<const float4*>(red)[(q * 8 + ob) * 32 + oj];
            sum.x += p.x; sum.y += p.y; sum.z += p.z; sum.w += p.w;
        }

        // LSTM cell + phased time gate
        float it = sigf(Gi + sum.x);
        float ft = sigf(Gf + sum.y);
        float gt = tanhf(Gg + sum.z);
        float ot = sigf(Go + sum.w);
        float cn = ft * ccar + it * gt;
        float hn = ot * tanhf(cn);

        float ic = fmodf(tt + sv, pv);
        float mask;
        if (ic <= on_mid)      mask = ic / on_mid;
        else if (ic <= on_end) mask = (on_end - ic) / on_mid;
        else                   mask = OFF_SLOPE * (ic / pv);

        ccar = mask * cn + (1.f - mask) * ccar;
        float h2 = mask * hn + (1.f - mask) * hcar;
        hcar = h2;

        // publish h, then per-warp release-arrive (fire-and-forget)
        g_hbuf[nxt][(bg0 + ob) * H_ + jg] = h2;
        __syncwarp();
        if (lane == 0) red_release(cnt);

        // off the critical path: output store + next-step prefetch
        out[((size_t)(bg0 + ob) * S_ + s) * H_ + jg] = h2;
        if (s + 1 < S_) {
            const float* Gp = Gbase + (size_t)(s + 1) * 1024;
            Gi = Gp[0]; Gf = Gp[256]; Gg = Gp[512]; Go = Gp[768];
            tt = tsrow[s + 1];
        }
    }

    if (writeTails) {
        const size_t baseT = (size_t)B_ * S_ * H_;
        out[baseT + (size_t)(bg0 + ob) * H_ + jg] = hcar;                    // h_T
        out[baseT + (size_t)B_ * H_ + (size_t)(bg0 + ob) * H_ + jg] = ccar;  // c_T
    }
}

// ---------------- launch ----------------
extern "C" void kernel_launch(void* const* d_in, const int* in_sizes, int n_in,
                              void* d_out, int out_size) {
    const float* x    = (const float*)d_in[0];
    const float* ts   = (const float*)d_in[1];
    const float* W    = (const float*)d_in[2];
    const float* U    = (const float*)d_in[3];
    const float* bias = (const float*)d_in[4];
    const float* Per  = (const float*)d_in[5];
    const float* Shf  = (const float*)d_in[6];
    const float* Oe   = (const float*)d_in[7];
    float* out = (float*)d_out;

    init_k<<<64, 256>>>();

    dim3 gg(131072 / 64, 1024 / 128);
    gemm_xw<<<gg, 256>>>(x, W, bias);

    const long long need = (long long)B_ * S_ * H_ + 2LL * B_ * H_;
    int writeTails = ((long long)out_size >= need) ? 1 : 0;
    plstm_rec<<<128, 256>>>(U, ts, Per, Shf, Oe, out, writeTails);
}

// round 5
// speedup vs baseline: 1.9702x; 1.9046x over previous
#include <cuda_runtime.h>
#include <cuda_bf16.h>
#include <cstdint>

#define B_   128
#define S_   1024
#define I_   128
#define H_   256
#define OFF_SLOPE 0.001f

// ---------------- device scratch (static, no allocations) ----------------
__device__ __align__(16) float g_G[134217728];          // [B*S][1024] = 512 MB
__device__ __align__(16) unsigned g_hpack[2][B_ * H_];  // packed (bf16 hi | lo<<16)
__device__ unsigned g_cnt[16];                          // per-group barrier counters

// ---------------- init: reset counters + h0 = 0 (every launch/replay) ----
__global__ void init_k() {
    unsigned t = blockIdx.x * blockDim.x + threadIdx.x;
    if (t < 16) g_cnt[t] = 0u;
    for (unsigned i = t; i < 2u * B_ * H_; i += gridDim.x * blockDim.x)
        ((unsigned*)g_hpack)[i] = 0u;
}

// ---------------- phase A: G = x @ W + bias  (fp32 tiled SGEMM) ----------
__global__ __launch_bounds__(256) void gemm_xw(const float* __restrict__ X,
                                               const float* __restrict__ Wm,
                                               const float* __restrict__ bias) {
    __shared__ __align__(16) float As[32][68];
    __shared__ __align__(16) float Bs[32][128];
    const int m0 = blockIdx.x * 64;
    const int n0 = blockIdx.y * 128;
    const int tid = threadIdx.x;
    const int tx = tid & 31, ty = tid >> 5;

    float4 acc[8];
#pragma unroll
    for (int r = 0; r < 8; r++) acc[r] = make_float4(0.f, 0.f, 0.f, 0.f);

    for (int kt = 0; kt < 128; kt += 32) {
#pragma unroll
        for (int i = 0; i < 2; i++) {
            int lin = tid + i * 256;
            int m = lin >> 3, k4 = lin & 7;
            float4 v = reinterpret_cast<const float4*>(X)[(size_t)(m0 + m) * 32 + (kt >> 2) + k4];
            As[k4 * 4 + 0][m] = v.x; As[k4 * 4 + 1][m] = v.y;
            As[k4 * 4 + 2][m] = v.z; As[k4 * 4 + 3][m] = v.w;
        }
#pragma unroll
        for (int i = 0; i < 4; i++) {
            int lin = tid + i * 256;
            int k = lin >> 5, n4 = lin & 31;
            reinterpret_cast<float4*>(&Bs[k][0])[n4] =
                reinterpret_cast<const float4*>(Wm)[(size_t)(kt + k) * 256 + (n0 >> 2) + n4];
        }
        __syncthreads();
#pragma unroll
        for (int k = 0; k < 32; k++) {
            float4 b4 = reinterpret_cast<float4*>(&Bs[k][0])[tx];
            const float4* Ap = reinterpret_cast<const float4*>(&As[k][ty * 8]);
            float4 a0 = Ap[0], a1 = Ap[1];
            float am[8] = {a0.x, a0.y, a0.z, a0.w, a1.x, a1.y, a1.z, a1.w};
#pragma unroll
            for (int r = 0; r < 8; r++) {
                acc[r].x += am[r] * b4.x; acc[r].y += am[r] * b4.y;
                acc[r].z += am[r] * b4.z; acc[r].w += am[r] * b4.w;
            }
        }
        __syncthreads();
    }
    float4 bv = reinterpret_cast<const float4*>(bias)[(n0 >> 2) + tx];
#pragma unroll
    for (int r = 0; r < 8; r++) {
        int m = m0 + ty * 8 + r;
        float4 o = acc[r];
        o.x += bv.x; o.y += bv.y; o.z += bv.z; o.w += bv.w;
        reinterpret_cast<float4*>(g_G)[(size_t)m * 256 + (n0 >> 2) + tx] = o;
    }
}

// ---------------- phase B: persistent recurrent kernel (HMMA) ------------
__device__ __forceinline__ float sigf(float x) { return 1.0f / (1.0f + __expf(-x)); }

__device__ __forceinline__ unsigned ld_acq(const unsigned* p) {
    unsigned v;
    asm volatile("ld.global.acquire.gpu.u32 %0, [%1];" : "=r"(v) : "l"(p) : "memory");
    return v;
}

__device__ __forceinline__ void mma_bf16(float4& d, const uint32_t* a,
                                         uint32_t b0, uint32_t b1) {
    asm volatile(
        "mma.sync.aligned.m16n8k16.row.col.f32.bf16.bf16.f32 "
        "{%0,%1,%2,%3}, {%4,%5,%6,%7}, {%8,%9}, {%0,%1,%2,%3};"
        : "+f"(d.x), "+f"(d.y), "+f"(d.z), "+f"(d.w)
        : "r"(a[0]), "r"(a[1]), "r"(a[2]), "r"(a[3]), "r"(b0), "r"(b1));
}

__device__ __forceinline__ void split_pack(float x, float y,
                                           uint32_t& hi, uint32_t& lo) {
    __nv_bfloat16 hx = __float2bfloat16(x);
    __nv_bfloat16 hy = __float2bfloat16(y);
    __nv_bfloat16 lx = __float2bfloat16(x - __bfloat162float(hx));
    __nv_bfloat16 ly = __float2bfloat16(y - __bfloat162float(hy));
    hi = (uint32_t)__bfloat16_as_ushort(hx) | ((uint32_t)__bfloat16_as_ushort(hy) << 16);
    lo = (uint32_t)__bfloat16_as_ushort(lx) | ((uint32_t)__bfloat16_as_ushort(ly) << 16);
}

// 128 CTAs = 16 groups (8 batches) x 8 slices (32 h-units = 128 gate rows).
// Per CTA: D[128 gates, 8 batches] = U^T_slice[128,256] @ h^T[256,8] via
// mma.sync bf16x3 (fp32-equivalent precision). U frags register-resident.
// Warp w owns M-rows [16w,16w+16), full K=256 -> no cross-warp reduction.
__global__ __launch_bounds__(256, 1) void plstm_rec(
    const float* __restrict__ U, const float* __restrict__ ts,
    const float* __restrict__ Per, const float* __restrict__ Shf,
    const float* __restrict__ Oe, float* __restrict__ out, int writeTails) {
    __shared__ __align__(16) uint32_t Hhi[8 * 132];   // h hi pairs, padded pitch 132
    __shared__ __align__(16) uint32_t Hlo[8 * 132];   // h lo pairs
    __shared__ __align__(16) float d_sm[128 * 10];    // D scatter, pitch 10

    const int tid = threadIdx.x;
    const int lane = tid & 31;
    const int w = tid >> 5;          // warp id = M-tile
    const int gp = lane >> 2;        // mma group id (0..7)
    const int t4 = lane & 3;         // mma thread-in-group (0..3)
    const int grp = blockIdx.x >> 3;
    const int hslc = blockIdx.x & 7;
    const int bg0 = grp * 8;
    const int hs = hslc * 32;
    const int ob = tid >> 5;         // owner role: batch in group
    const int oj = lane;             // owner role: h-unit in slice
    const int jg = hs + oj;
    unsigned* cnt = &g_cnt[grp];

    const float pv = fabsf(Per[jg]);
    const float sv = Shf[jg];
    const float oe = fabsf(Oe[jg]);
    const float on_end = oe * pv;
    const float on_mid = (oe * 0.5f) * pv;

    // ---- one-time: preload U^T fragments (hi/lo bf16 split) ----
    // warp w covers gate block gblk = w>>1, units u0 + gp (+8); row r=16w+gp.
    uint32_t Ahi[16][4], Alo[16][4];
    {
        const int gblk = w >> 1;
        const int u0 = (w & 1) * 16;
        const int gc0 = gblk * 256 + hs + u0 + gp;      // rows a0/a2
        const int gc1 = gc0 + 8;                         // rows a1/a3
#pragma unroll
        for (int q = 0; q < 16; q++) {
            const int k0 = q * 16 + 2 * t4;
            float x, y;
            x = U[(size_t)k0 * 1024 + gc0];       y = U[(size_t)(k0 + 1) * 1024 + gc0];
            split_pack(x, y, Ahi[q][0], Alo[q][0]);
            x = U[(size_t)k0 * 1024 + gc1];       y = U[(size_t)(k0 + 1) * 1024 + gc1];
            split_pack(x, y, Ahi[q][1], Alo[q][1]);
            x = U[(size_t)(k0 + 8) * 1024 + gc0]; y = U[(size_t)(k0 + 9) * 1024 + gc0];
            split_pack(x, y, Ahi[q][2], Alo[q][2]);
            x = U[(size_t)(k0 + 8) * 1024 + gc1]; y = U[(size_t)(k0 + 9) * 1024 + gc1];
            split_pack(x, y, Ahi[q][3], Alo[q][3]);
        }
    }

    float ccar = 0.f, hcar = 0.f;
    const float* tsrow = ts + (size_t)(bg0 + ob) * S_;
    const float* Gbase = g_G + (size_t)(bg0 + ob) * S_ * 1024 + hs + oj;

    // prefetch step-0 owner inputs
    float Gi = Gbase[0], Gf = Gbase[256], Gg = Gbase[512], Go = Gbase[768];
    float tt = tsrow[0];

    for (int s = 0; s < S_; s++) {
        const int cur = s & 1, nxt = cur ^ 1;

        // ---- stage packed h -> SMEM hi/lo pair arrays ----
        // thread (b = w, k = lane*8..lane*8+7) of this group's 8x256 units
        {
            const uint4* src = reinterpret_cast<const uint4*>(
                &g_hpack[cur][(bg0 + w) * H_ + lane * 8]);
            uint4 p0 = src[0], p1 = src[1];
            const int dst = w * 132 + lane * 4;
            Hhi[dst + 0] = __byte_perm(p0.x, p0.y, 0x5410);
            Hlo[dst + 0] = __byte_perm(p0.x, p0.y, 0x7632);
            Hhi[dst + 1] = __byte_perm(p0.z, p0.w, 0x5410);
            Hlo[dst + 1] = __byte_perm(p0.z, p0.w, 0x7632);
            Hhi[dst + 2] = __byte_perm(p1.x, p1.y, 0x5410);
            Hlo[dst + 2] = __byte_perm(p1.x, p1.y, 0x7632);
            Hhi[dst + 3] = __byte_perm(p1.z, p1.w, 0x5410);
            Hlo[dst + 3] = __byte_perm(p1.z, p1.w, 0x7632);
        }
        __syncthreads();

        // ---- MMA: D[16w..16w+16, 8 batches], K=256, bf16x3 ----
        float4 D = make_float4(0.f, 0.f, 0.f, 0.f);
#pragma unroll
        for (int q = 0; q < 16; q++) {
            const int base = gp * 132 + q * 8 + t4;
            uint32_t bh0 = Hhi[base], bh1 = Hhi[base + 4];
            uint32_t bl0 = Hlo[base], bl1 = Hlo[base + 4];
            mma_bf16(D, Ahi[q], bh0, bh1);
            mma_bf16(D, Ahi[q], bl0, bl1);
            mma_bf16(D, Alo[q], bh0, bh1);
        }

        // scatter D to SMEM: rows 16w+gp (+8), cols 2t4 (+1)
        {
            const int r0 = 16 * w + gp;
            d_sm[r0 * 10 + 2 * t4] = D.x;
            d_sm[r0 * 10 + 2 * t4 + 1] = D.y;
            d_sm[(r0 + 8) * 10 + 2 * t4] = D.z;
            d_sm[(r0 + 8) * 10 + 2 * t4 + 1] = D.w;
        }
        __syncthreads();

        // ---- cell: owner (ob, oj) gathers its 4 gate preactivations ----
        float p0 = d_sm[(0 * 32 + oj) * 10 + ob];
        float p1 = d_sm[(1 * 32 + oj) * 10 + ob];
        float p2 = d_sm[(2 * 32 + oj) * 10 + ob];
        float p3 = d_sm[(3 * 32 + oj) * 10 + ob];

        float it = sigf(Gi + p0);
        float ft = sigf(Gf + p1);
        float gt = tanhf(Gg + p2);
        float ot = sigf(Go + p3);
        float cn = ft * ccar + it * gt;
        float hn = ot * tanhf(cn);

        float ic = fmodf(tt + sv, pv);
        float mask;
        if (ic <= on_mid)      mask = ic / on_mid;
        else if (ic <= on_end) mask = (on_end - ic) / on_mid;
        else                   mask = OFF_SLOPE * (ic / pv);

        ccar = mask * cn + (1.f - mask) * ccar;
        float h2 = mask * hn + (1.f - mask) * hcar;
        hcar = h2;

        // publish packed h + output
        {
            __nv_bfloat16 hb = __float2bfloat16(h2);
            __nv_bfloat16 lb = __float2bfloat16(h2 - __bfloat162float(hb));
            g_hpack[nxt][(bg0 + ob) * H_ + jg] =
                (uint32_t)__bfloat16_as_ushort(hb) |
                ((uint32_t)__bfloat16_as_ushort(lb) << 16);
        }
        out[((size_t)(bg0 + ob) * S_ + s) * H_ + jg] = h2;

        // group barrier (8 CTAs, monotonic counter) — round-1 verified form
        __syncthreads();
        if (tid == 0) {
            __threadfence();
            atomicAdd(cnt, 1u);
            const unsigned tgt = 8u * (unsigned)(s + 1);
            while (ld_acq(cnt) < tgt) {}
        }
        __syncthreads();

        // next-step prefetch (off critical path of other CTAs)
        if (s + 1 < S_) {
            const float* Gp = Gbase + (size_t)(s + 1) * 1024;
            Gi = Gp[0]; Gf = Gp[256]; Gg = Gp[512]; Go = Gp[768];
            tt = tsrow[s + 1];
        }
    }

    if (writeTails) {
        const size_t baseT = (size_t)B_ * S_ * H_;
        out[baseT + (size_t)(bg0 + ob) * H_ + jg] = hcar;                    // h_T
        out[baseT + (size_t)B_ * H_ + (size_t)(bg0 + ob) * H_ + jg] = ccar;  // c_T
    }
}

// ---------------- launch ----------------
extern "C" void kernel_launch(void* const* d_in, const int* in_sizes, int n_in,
                              void* d_out, int out_size) {
    const float* x    = (const float*)d_in[0];
    const float* ts   = (const float*)d_in[1];
    const float* W    = (const float*)d_in[2];
    const float* U    = (const float*)d_in[3];
    const float* bias = (const float*)d_in[4];
    const float* Per  = (const float*)d_in[5];
    const float* Shf  = (const float*)d_in[6];
    const float* Oe   = (const float*)d_in[7];
    float* out = (float*)d_out;

    init_k<<<64, 256>>>();

    dim3 gg(131072 / 64, 1024 / 128);
    gemm_xw<<<gg, 256>>>(x, W, bias);

    const long long need = (long long)B_ * S_ * H_ + 2LL * B_ * H_;
    int writeTails = ((long long)out_size >= need) ? 1 : 0;
    plstm_rec<<<128, 256>>>(U, ts, Per, Shf, Oe, out, writeTails);
}

// round 6
// speedup vs baseline: 2.3319x; 1.1836x over previous
#include <cuda_runtime.h>
#include <cuda_bf16.h>
#include <cstdint>

#define B_   128
#define S_   1024
#define I_   128
#define H_   256
#define OFF_SLOPE 0.001f

// ---------------- device scratch (static, no allocations) ----------------
__device__ __align__(16) float g_G[134217728];          // [B*S][1024] = 512 MB
__device__ __align__(16) unsigned g_hpack[2][B_ * H_];  // packed (bf16 hi | lo<<16)
__device__ unsigned g_cnt[16];                          // per-group barrier counters

__device__ __forceinline__ void split_pack(float x, float y,
                                           uint32_t& hi, uint32_t& lo) {
    __nv_bfloat16 hx = __float2bfloat16(x);
    __nv_bfloat16 hy = __float2bfloat16(y);
    __nv_bfloat16 lx = __float2bfloat16(x - __bfloat162float(hx));
    __nv_bfloat16 ly = __float2bfloat16(y - __bfloat162float(hy));
    hi = (uint32_t)__bfloat16_as_ushort(hx) | ((uint32_t)__bfloat16_as_ushort(hy) << 16);
    lo = (uint32_t)__bfloat16_as_ushort(lx) | ((uint32_t)__bfloat16_as_ushort(ly) << 16);
}

__device__ __forceinline__ void mma_bf16(float4& d, const uint32_t* a,
                                         uint32_t b0, uint32_t b1) {
    asm volatile(
        "mma.sync.aligned.m16n8k16.row.col.f32.bf16.bf16.f32 "
        "{%0,%1,%2,%3}, {%4,%5,%6,%7}, {%8,%9}, {%0,%1,%2,%3};"
        : "+f"(d.x), "+f"(d.y), "+f"(d.z), "+f"(d.w)
        : "r"(a[0]), "r"(a[1]), "r"(a[2]), "r"(a[3]), "r"(b0), "r"(b1));
}

// ---------------- init: reset counters + h0 = 0 (every launch/replay) ----
__global__ void init_k() {
    unsigned t = blockIdx.x * blockDim.x + threadIdx.x;
    if (t < 16) g_cnt[t] = 0u;
    for (unsigned i = t; i < 2u * B_ * H_; i += gridDim.x * blockDim.x)
        ((unsigned*)g_hpack)[i] = 0u;
}

// ---------------- phase A: G = x @ W + bias  (bf16x3 tensor-core GEMM) ---
// M=131072, N=1024, K=128 (single K pass). CTA tile 128x128, 8 warps of
// 32(M) x 64(N). x and W split to bf16 hi/lo in SMEM; D = xh*Wh + xh*Wl +
// xl*Wh, fp32 accumulate (fp32-equivalent precision).
__global__ __launch_bounds__(256) void gemm_xw_mma(const float* __restrict__ X,
                                                   const float* __restrict__ Wm,
                                                   const float* __restrict__ bias) {
    extern __shared__ uint32_t sm[];
    uint32_t* Axh = sm;                    // [128][66] k-pair u32
    uint32_t* Axl = Axh + 128 * 66;
    uint32_t* Bnh = Axl + 128 * 66;        // [128 n][66] k-pair u32
    uint32_t* Bnl = Bnh + 128 * 66;

    const int m0 = blockIdx.x * 128;
    const int n0 = blockIdx.y * 128;
    const int tid = threadIdx.x;
    const int lane = tid & 31, w = tid >> 5;
    const int gp = lane >> 2, t4 = lane & 3;
    const int wm = w >> 1, wn = w & 1;

    // load + convert x tile [128 m][128 k] (coalesced float4)
#pragma unroll
    for (int j = 0; j < 16; j++) {
        int lin = tid + j * 256;            // 0..4095 over 128x32 float4 grid
        int m = lin >> 5, c = lin & 31;
        float4 v = reinterpret_cast<const float4*>(X)[(size_t)(m0 + m) * 32 + c];
        uint32_t h0, l0, h1, l1;
        split_pack(v.x, v.y, h0, l0);
        split_pack(v.z, v.w, h1, l1);
        Axh[m * 66 + 2 * c] = h0; Axh[m * 66 + 2 * c + 1] = h1;
        Axl[m * 66 + 2 * c] = l0; Axl[m * 66 + 2 * c + 1] = l1;
    }
    // load + convert W tile [128 k][128 n] -> [n][kpair] (coalesced over n)
    {
        const int n = tid & 127, kh = tid >> 7;     // kh in {0,1}: 64 k's each
        const float* wp = Wm + (size_t)(kh * 64) * 1024 + n0 + n;
        uint32_t* dh = &Bnh[n * 66 + kh * 32];
        uint32_t* dl = &Bnl[n * 66 + kh * 32];
#pragma unroll
        for (int j = 0; j < 32; j++) {
            float a = wp[(size_t)(2 * j) * 1024];
            float b = wp[(size_t)(2 * j + 1) * 1024];
            uint32_t h, l; split_pack(a, b, h, l);
            dh[j] = h; dl[j] = l;
        }
    }
    __syncthreads();

    float4 acc[2][8];
#pragma unroll
    for (int mt = 0; mt < 2; mt++)
#pragma unroll
        for (int nt = 0; nt < 8; nt++) acc[mt][nt] = make_float4(0.f, 0.f, 0.f, 0.f);

#pragma unroll
    for (int ks = 0; ks < 8; ks++) {
        uint32_t ah[2][4], al[2][4];
#pragma unroll
        for (int mt = 0; mt < 2; mt++) {
            const int r0 = (wm * 32 + mt * 16 + gp) * 66 + ks * 8;
            ah[mt][0] = Axh[r0 + t4];       ah[mt][1] = Axh[r0 + 8 * 66 + t4];
            ah[mt][2] = Axh[r0 + t4 + 4];   ah[mt][3] = Axh[r0 + 8 * 66 + t4 + 4];
            al[mt][0] = Axl[r0 + t4];       al[mt][1] = Axl[r0 + 8 * 66 + t4];
            al[mt][2] = Axl[r0 + t4 + 4];   al[mt][3] = Axl[r0 + 8 * 66 + t4 + 4];
        }
#pragma unroll
        for (int nt = 0; nt < 8; nt++) {
            const int c0 = (wn * 64 + nt * 8 + gp) * 66 + ks * 8;
            uint32_t bh0 = Bnh[c0 + t4], bh1 = Bnh[c0 + t4 + 4];
            uint32_t bl0 = Bnl[c0 + t4], bl1 = Bnl[c0 + t4 + 4];
#pragma unroll
            for (int mt = 0; mt < 2; mt++) {
                mma_bf16(acc[mt][nt], ah[mt], bh0, bh1);
                mma_bf16(acc[mt][nt], ah[mt], bl0, bl1);
                mma_bf16(acc[mt][nt], al[mt], bh0, bh1);
            }
        }
    }

    // epilogue: + bias, store fp32 G
#pragma unroll
    for (int nt = 0; nt < 8; nt++) {
        const int n = n0 + wn * 64 + nt * 8 + 2 * t4;
        float2 bv = *reinterpret_cast<const float2*>(bias + n);
#pragma unroll
        for (int mt = 0; mt < 2; mt++) {
            const int m = m0 + wm * 32 + mt * 16 + gp;
            float4 d = acc[mt][nt];
            *reinterpret_cast<float2*>(&g_G[(size_t)m * 1024 + n]) =
                make_float2(d.x + bv.x, d.y + bv.y);
            *reinterpret_cast<float2*>(&g_G[(size_t)(m + 8) * 1024 + n]) =
                make_float2(d.z + bv.x, d.w + bv.y);
        }
    }
}

// ---------------- phase B: persistent recurrent kernel (HMMA) ------------
__device__ __forceinline__ float sigf(float x) { return 1.0f / (1.0f + __expf(-x)); }

__device__ __forceinline__ unsigned ld_acq(const unsigned* p) {
    unsigned v;
    asm volatile("ld.global.acquire.gpu.u32 %0, [%1];" : "=r"(v) : "l"(p) : "memory");
    return v;
}
__device__ __forceinline__ void red_release(unsigned* p) {
    unsigned one = 1u;
    asm volatile("red.release.gpu.global.add.u32 [%0], %1;" :: "l"(p), "r"(one) : "memory");
}
__device__ __forceinline__ uint4 ldcg_u4(const uint4* p) {
    uint4 v;
    asm volatile("ld.global.cg.v4.u32 {%0,%1,%2,%3}, [%4];"
                 : "=r"(v.x), "=r"(v.y), "=r"(v.z), "=r"(v.w) : "l"(p));
    return v;
}

// 128 CTAs = 16 groups (8 batches) x 8 slices (32 h-units = 128 gate rows).
// D[128 gates, 8 batches] = U^T_slice[128,256] @ h^T[256,8] via mma.sync
// bf16x3 with 3 independent accumulator chains. U frags register-resident.
__global__ __launch_bounds__(256, 1) void plstm_rec(
    const float* __restrict__ U, const float* __restrict__ ts,
    const float* __restrict__ Per, const float* __restrict__ Shf,
    const float* __restrict__ Oe, float* __restrict__ out, int writeTails) {
    __shared__ __align__(16) uint32_t Hhi[8 * 132];
    __shared__ __align__(16) uint32_t Hlo[8 * 132];
    __shared__ __align__(16) float d_sm[128 * 10];

    const int tid = threadIdx.x;
    const int lane = tid & 31;
    const int w = tid >> 5;
    const int gp = lane >> 2;
    const int t4 = lane & 3;
    const int grp = blockIdx.x >> 3;
    const int hslc = blockIdx.x & 7;
    const int bg0 = grp * 8;
    const int hs = hslc * 32;
    const int ob = tid >> 5;
    const int oj = lane;
    const int jg = hs + oj;
    unsigned* cnt = &g_cnt[grp];

    const float pv = fabsf(Per[jg]);
    const float sv = Shf[jg];
    const float oe = fabsf(Oe[jg]);
    const float on_end = oe * pv;
    const float on_mid = (oe * 0.5f) * pv;

    // one-time: preload U^T fragments (hi/lo bf16 split)
    uint32_t Ahi[16][4], Alo[16][4];
    {
        const int gblk = w >> 1;
        const int u0 = (w & 1) * 16;
        const int gc0 = gblk * 256 + hs + u0 + gp;
        const int gc1 = gc0 + 8;
#pragma unroll
        for (int q = 0; q < 16; q++) {
            const int k0 = q * 16 + 2 * t4;
            float x, y;
            x = U[(size_t)k0 * 1024 + gc0];       y = U[(size_t)(k0 + 1) * 1024 + gc0];
            split_pack(x, y, Ahi[q][0], Alo[q][0]);
            x = U[(size_t)k0 * 1024 + gc1];       y = U[(size_t)(k0 + 1) * 1024 + gc1];
            split_pack(x, y, Ahi[q][1], Alo[q][1]);
            x = U[(size_t)(k0 + 8) * 1024 + gc0]; y = U[(size_t)(k0 + 9) * 1024 + gc0];
            split_pack(x, y, Ahi[q][2], Alo[q][2]);
            x = U[(size_t)(k0 + 8) * 1024 + gc1]; y = U[(size_t)(k0 + 9) * 1024 + gc1];
            split_pack(x, y, Ahi[q][3], Alo[q][3]);
        }
    }

    float ccar = 0.f, hcar = 0.f;
    const float* tsrow = ts + (size_t)(bg0 + ob) * S_;
    const float* Gbase = g_G + (size_t)(bg0 + ob) * S_ * 1024 + hs + oj;

    float Gi = Gbase[0], Gf = Gbase[256], Gg = Gbase[512], Go = Gbase[768];
    float tt = tsrow[0];

    for (int s = 0; s < S_; s++) {
        const int cur = s & 1, nxt = cur ^ 1;

        // stage packed h -> SMEM hi/lo pair arrays (L2-coherent loads)
        {
            const uint4* src = reinterpret_cast<const uint4*>(
                &g_hpack[cur][(bg0 + w) * H_ + lane * 8]);
            uint4 p0 = ldcg_u4(src), p1 = ldcg_u4(src + 1);
            const int dst = w * 132 + lane * 4;
            Hhi[dst + 0] = __byte_perm(p0.x, p0.y, 0x5410);
            Hlo[dst + 0] = __byte_perm(p0.x, p0.y, 0x7632);
            Hhi[dst + 1] = __byte_perm(p0.z, p0.w, 0x5410);
            Hlo[dst + 1] = __byte_perm(p0.z, p0.w, 0x7632);
            Hhi[dst + 2] = __byte_perm(p1.x, p1.y, 0x5410);
            Hlo[dst + 2] = __byte_perm(p1.x, p1.y, 0x7632);
            Hhi[dst + 3] = __byte_perm(p1.z, p1.w, 0x5410);
            Hlo[dst + 3] = __byte_perm(p1.z, p1.w, 0x7632);
        }
        __syncthreads();

        // MMA with 3 independent accumulator chains
        float4 Da = make_float4(0.f, 0.f, 0.f, 0.f);
        float4 Db = make_float4(0.f, 0.f, 0.f, 0.f);
        float4 Dc = make_float4(0.f, 0.f, 0.f, 0.f);
#pragma unroll
        for (int q = 0; q < 16; q++) {
            const int base = gp * 132 + q * 8 + t4;
            uint32_t bh0 = Hhi[base], bh1 = Hhi[base + 4];
            uint32_t bl0 = Hlo[base], bl1 = Hlo[base + 4];
            mma_bf16(Da, Ahi[q], bh0, bh1);
            mma_bf16(Db, Ahi[q], bl0, bl1);
            mma_bf16(Dc, Alo[q], bh0, bh1);
        }
        float4 D = make_float4(Da.x + Db.x + Dc.x, Da.y + Db.y + Dc.y,
                               Da.z + Db.z + Dc.z, Da.w + Db.w + Dc.w);

        {
            const int r0 = 16 * w + gp;
            d_sm[r0 * 10 + 2 * t4] = D.x;
            d_sm[r0 * 10 + 2 * t4 + 1] = D.y;
            d_sm[(r0 + 8) * 10 + 2 * t4] = D.z;
            d_sm[(r0 + 8) * 10 + 2 * t4 + 1] = D.w;
        }
        __syncthreads();

        float p0 = d_sm[(0 * 32 + oj) * 10 + ob];
        float p1 = d_sm[(1 * 32 + oj) * 10 + ob];
        float p2 = d_sm[(2 * 32 + oj) * 10 + ob];
        float p3 = d_sm[(3 * 32 + oj) * 10 + ob];

        float it = sigf(Gi + p0);
        float ft = sigf(Gf + p1);
        float gt = tanhf(Gg + p2);
        float ot = sigf(Go + p3);
        float cn = ft * ccar + it * gt;
        float hn = ot * tanhf(cn);

        float ic = fmodf(tt + sv, pv);
        float mask;
        if (ic <= on_mid)      mask = ic / on_mid;
        else if (ic <= on_end) mask = (on_end - ic) / on_mid;
        else                   mask = OFF_SLOPE * (ic / pv);

        ccar = mask * cn + (1.f - mask) * ccar;
        float h2 = mask * hn + (1.f - mask) * hcar;
        hcar = h2;

        // publish packed h + output
        {
            __nv_bfloat16 hb = __float2bfloat16(h2);
            __nv_bfloat16 lb = __float2bfloat16(h2 - __bfloat162float(hb));
            g_hpack[nxt][(bg0 + ob) * H_ + jg] =
                (uint32_t)__bfloat16_as_ushort(hb) |
                ((uint32_t)__bfloat16_as_ushort(lb) << 16);
        }
        out[((size_t)(bg0 + ob) * S_ + s) * H_ + jg] = h2;

        // next-step prefetch launched BEFORE the barrier (in flight during wait)
        if (s + 1 < S_) {
            const float* Gp = Gbase + (size_t)(s + 1) * 1024;
            Gi = Gp[0]; Gf = Gp[256]; Gg = Gp[512]; Go = Gp[768];
            tt = tsrow[s + 1];
        }

        // group barrier: release-arrive (no return trip) + acquire-poll
        __syncthreads();
        if (tid == 0) {
            red_release(cnt);
            const unsigned tgt = 8u * (unsigned)(s + 1);
            while (ld_acq(cnt) < tgt) {}
        }
        __syncthreads();
    }

    if (writeTails) {
        const size_t baseT = (size_t)B_ * S_ * H_;
        out[baseT + (size_t)(bg0 + ob) * H_ + jg] = hcar;                    // h_T
        out[baseT + (size_t)B_ * H_ + (size_t)(bg0 + ob) * H_ + jg] = ccar;  // c_T
    }
}

// ---------------- launch ----------------
extern "C" void kernel_launch(void* const* d_in, const int* in_sizes, int n_in,
                              void* d_out, int out_size) {
    const float* x    = (const float*)d_in[0];
    const float* ts   = (const float*)d_in[1];
    const float* W    = (const float*)d_in[2];
    const float* U    = (const float*)d_in[3];
    const float* bias = (const float*)d_in[4];
    const float* Per  = (const float*)d_in[5];
    const float* Shf  = (const float*)d_in[6];
    const float* Oe   = (const float*)d_in[7];
    float* out = (float*)d_out;

    init_k<<<64, 256>>>();

    const int smA = 4 * 128 * 66 * 4;   // 135168 B dynamic SMEM
    cudaFuncSetAttribute(gemm_xw_mma, cudaFuncAttributeMaxDynamicSharedMemorySize, smA);
    dim3 gg(131072 / 128, 1024 / 128);
    gemm_xw_mma<<<gg, 256, smA>>>(x, W, bias);

    const long long need = (long long)B_ * S_ * H_ + 2LL * B_ * H_;
    int writeTails = ((long long)out_size >= need) ? 1 : 0;
    plstm_rec<<<128, 256>>>(U, ts, Per, Shf, Oe, out, writeTails);
}